// round 15
// baseline (speedup 1.0000x reference)
#include <cuda_runtime.h>
#include <cuda_fp16.h>
#include <stdint.h>

#define NH   8
#define HD   64
#define NTOK 4096
#define EMB  512
#define CIN  512

// Scratch Q/K/V in [b][h][n][d] layout, fp16.  Q pre-scaled by 0.125*log2(e).
__device__ __half g_Q[2*NH*NTOK*HD];
__device__ __half g_K[2*NH*NTOK*HD];
__device__ __half g_V[2*NH*NTOK*HD];

// ---------------------------------------------------------------------------
__device__ __forceinline__ float ex2f(float x){
    float r; asm("ex2.approx.ftz.f32 %0, %1;" : "=f"(r) : "f"(x)); return r;
}
__device__ __forceinline__ uint32_t smem_u32(const void* p) {
    uint32_t a;
    asm("{ .reg .u64 t; cvta.to.shared.u64 t, %1; cvt.u32.u64 %0, t; }" : "=r"(a) : "l"(p));
    return a;
}
__device__ __forceinline__ uint32_t pack2(float x, float y){
    __half2 h = __floats2half2_rn(x, y);
    return *(uint32_t*)&h;
}
// fp16 mma, fp32 accum
__device__ __forceinline__ void mma16(float* c, const uint32_t* a, uint32_t b0, uint32_t b1){
    asm volatile("mma.sync.aligned.m16n8k16.row.col.f32.f16.f16.f32 "
        "{%0,%1,%2,%3},{%4,%5,%6,%7},{%8,%9},{%0,%1,%2,%3};"
        : "+f"(c[0]),"+f"(c[1]),"+f"(c[2]),"+f"(c[3])
        : "r"(a[0]),"r"(a[1]),"r"(a[2]),"r"(a[3]),"r"(b0),"r"(b1));
}
#define LDSM4(r, a) \
    asm volatile("ldmatrix.sync.aligned.m8n8.x4.shared.b16 {%0,%1,%2,%3}, [%4];" \
        : "=r"((r)[0]),"=r"((r)[1]),"=r"((r)[2]),"=r"((r)[3]) : "r"(a))
#define LDSM4T(r, a) \
    asm volatile("ldmatrix.sync.aligned.m8n8.x4.trans.shared.b16 {%0,%1,%2,%3}, [%4];" \
        : "=r"((r)[0]),"=r"((r)[1]),"=r"((r)[2]),"=r"((r)[3]) : "r"(a))
#define CP16(dst, src) asm volatile("cp.async.cg.shared.global [%0], [%1], 16;" :: "r"(dst), "l"(src) : "memory")
#define CP_COMMIT()    asm volatile("cp.async.commit_group;" ::: "memory")
#define CP_WAIT0()     asm volatile("cp.async.wait_group 0;" ::: "memory")
#define CP_WAIT1()     asm volatile("cp.async.wait_group 1;" ::: "memory")

// ---------------------------------------------------------------------------
// Projection (fp16 mma + ldmatrix): O[b][h][n][d] = X_tok @ W^T + bias.
// (unchanged from round 11: ~60 us)
// ---------------------------------------------------------------------------
#define XSTR 136
#define WSTR 24

__global__ __launch_bounds__(256, 2) void proj_mma(
    const float* __restrict__ query, const float* __restrict__ key,
    const float* __restrict__ Wq, const float* __restrict__ bq,
    const float* __restrict__ Wk, const float* __restrict__ bk,
    const float* __restrict__ Wv, const float* __restrict__ bv)
{
    const int z = blockIdx.z;
    const float* X    = (z == 0) ? query : key;
    const float* W    = (z == 0) ? Wq : (z == 1 ? Wk : Wv);
    const float* bias = (z == 0) ? bq : (z == 1 ? bk : bv);
    __half* O         = (z == 0) ? g_Q : (z == 1 ? g_K : g_V);
    const float osc   = (z == 0) ? 0.18033688011112042f : 1.0f;  // 0.125*log2(e)

    const int b  = blockIdx.x >> 5;
    const int n0 = (blockIdx.x & 31) * 128;
    const int e0 = blockIdx.y * 128;

    __shared__ __align__(16) __half Xs[2][16*XSTR];
    __shared__ __align__(16) __half Ws[2][128*WSTR];

    const int tid = threadIdx.x, lane = tid & 31, w = tid >> 5;
    const int g = lane >> 2, t = lane & 3;
    const int wm = w >> 1, wn = w & 1;
    const int i8 = lane >> 3, lr = lane & 7;

    const int xc = tid >> 4, xn = (tid & 15) * 8;
    const int we = tid >> 1, wc = (tid & 1) * 8;

    const uint32_t aoff = (uint32_t)(((i8 >> 1)*8 + lr)*XSTR + (i8 & 1)*8);
    const uint32_t boff = (uint32_t)(((i8 >> 1)*8 + lr)*WSTR + (i8 & 1)*8);

    const size_t xbase = (size_t)b * CIN * NTOK;

    float acc[2][8][4];
    #pragma unroll
    for (int mb = 0; mb < 2; mb++)
        #pragma unroll
        for (int nb = 0; nb < 8; nb++)
            #pragma unroll
            for (int c = 0; c < 4; c++) acc[mb][nb][c] = 0.f;

    float4 xv0 = *(const float4*)&X[xbase + (size_t)xc * NTOK + n0 + xn];
    float4 xv1 = *(const float4*)&X[xbase + (size_t)xc * NTOK + n0 + xn + 4];
    float4 wv0 = *(const float4*)&W[(size_t)(e0 + we) * CIN + wc];
    float4 wv1 = *(const float4*)&W[(size_t)(e0 + we) * CIN + wc + 4];

    for (int kt = 0; kt < CIN/16; kt++) {
        const int cur = kt & 1;
        {
            uint4 ux = { pack2(xv0.x, xv0.y), pack2(xv0.z, xv0.w),
                         pack2(xv1.x, xv1.y), pack2(xv1.z, xv1.w) };
            *(uint4*)&Xs[cur][xc*XSTR + xn] = ux;
            uint4 uw = { pack2(wv0.x, wv0.y), pack2(wv0.z, wv0.w),
                         pack2(wv1.x, wv1.y), pack2(wv1.z, wv1.w) };
            *(uint4*)&Ws[cur][we*WSTR + wc] = uw;
        }
        __syncthreads();
        if (kt + 1 < CIN/16) {
            const int c0 = (kt + 1) * 16;
            xv0 = *(const float4*)&X[xbase + (size_t)(c0 + xc) * NTOK + n0 + xn];
            xv1 = *(const float4*)&X[xbase + (size_t)(c0 + xc) * NTOK + n0 + xn + 4];
            wv0 = *(const float4*)&W[(size_t)(e0 + we) * CIN + c0 + wc];
            wv1 = *(const float4*)&W[(size_t)(e0 + we) * CIN + c0 + wc + 4];
        }
        const uint32_t sX = smem_u32(&Xs[cur][0]);
        const uint32_t sW = smem_u32(&Ws[cur][0]);
        uint32_t a[2][4];
        #pragma unroll
        for (int mb = 0; mb < 2; mb++)
            LDSM4T(a[mb], sX + 2u*(aoff + (uint32_t)(wm*32 + mb*16)));
        #pragma unroll
        for (int nbp = 0; nbp < 4; nbp++) {
            uint32_t bf[4];
            LDSM4(bf, sW + 2u*(boff + (uint32_t)((wn*64 + nbp*16)*WSTR)));
            #pragma unroll
            for (int mb = 0; mb < 2; mb++) {
                mma16(acc[mb][2*nbp  ], a[mb], bf[0], bf[1]);
                mma16(acc[mb][2*nbp+1], a[mb], bf[2], bf[3]);
            }
        }
    }

    #pragma unroll
    for (int mb = 0; mb < 2; mb++) {
        #pragma unroll
        for (int nb = 0; nb < 8; nb++) {
            int e = e0 + wn*64 + nb*8 + 2*t;
            float2 bb = *(const float2*)&bias[e];
            int h = e >> 6, d = e & 63;
            int n = n0 + wm*32 + mb*16 + g;
            __half* o0 = &O[(((size_t)b*NH + h)*NTOK + n)*HD + d];
            *(__half2*)o0 = __floats2half2_rn((acc[mb][nb][0] + bb.x) * osc,
                                              (acc[mb][nb][1] + bb.y) * osc);
            *(__half2*)(o0 + 8*HD) = __floats2half2_rn((acc[mb][nb][2] + bb.x) * osc,
                                                       (acc[mb][nb][3] + bb.y) * osc);
        }
    }
}

// ---------------------------------------------------------------------------
// Flash attention, fp16 mma + ldmatrix, software-pipelined S:
// in iter j: softmax of S_j, then QK for tile j+1 INTERLEAVED with PV of j
// (independent mma streams -> tensor pipe stays busy across softmax).
// 3 K/V buffers, cp.async staged at distance 2.  P never touches smem.
// ---------------------------------------------------------------------------
#define KSTR 72
#define KB(i) ((i)*(64*KSTR))
#define VB(i) ((3 + (i))*(64*KSTR))
#define OFF_P (6*64*KSTR)          // 27648  (Q stage / fp32 out stage)
#define SMH   (OFF_P + 128*KSTR)   // 36864 halves = 73728 B
#define OSTR  132

__device__ __forceinline__ void stage_kv_async(uint32_t sb, const __half* Kg, const __half* Vg,
                                               int n0, int kOff, int vOff, int tid)
{
    #pragma unroll
    for (int it = 0; it < 2; it++) {
        int i = tid + it*256, r = i >> 3, c8 = (i & 7) * 8;
        CP16(sb + (uint32_t)(kOff + r*KSTR + c8)*2u, Kg + (size_t)(n0 + r)*HD + c8);
        CP16(sb + (uint32_t)(vOff + r*KSTR + c8)*2u, Vg + (size_t)(n0 + r)*HD + c8);
    }
}

__global__ __launch_bounds__(256, 2) void attn_mma(float* __restrict__ out)
{
    const int qt = 31 - (int)blockIdx.x;   // big tiles first
    const int h  = blockIdx.y;
    const int b  = blockIdx.z;

    extern __shared__ __align__(16) __half smh[];
    const uint32_t sbase = smem_u32(smh);

    const int tid = threadIdx.x, lane = tid & 31, w = tid >> 5;
    const int g = lane >> 2, t = lane & 3;
    const int r0 = w*16 + g;
    const int m  = lane >> 3, lr = lane & 7;

    // ldmatrix per-lane offsets (row stride 144 B)
    const uint32_t aQ  = sbase + (uint32_t)(OFF_P*2) + (uint32_t)(w*16 + (m&1)*8 + lr)*144u + (uint32_t)((m>>1)*8)*2u;
    const uint32_t aKo = (uint32_t)((m>>1)*8 + lr)*144u + (uint32_t)((m&1)*8)*2u;   // + buf base
    const uint32_t aVo = (uint32_t)((m&1)*8 + lr)*144u + (uint32_t)((m>>1)*8)*2u;   // + buf base

    const size_t base  = ((size_t)(b*NH + h)) * NTOK * HD;
    const int    qbase = qt * 128;
    const __half* Kg = g_K + base;
    const __half* Vg = g_V + base;
    const int ntiles = 2*qt + 2;   // >= 2 always

    // prologue: stage tiles 0,1 (async) + Q (sync)
    stage_kv_async(sbase, Kg, Vg, 0,  KB(0), VB(0), tid);
    CP_COMMIT();
    stage_kv_async(sbase, Kg, Vg, 64, KB(1), VB(1), tid);
    CP_COMMIT();
    #pragma unroll
    for (int it = 0; it < 4; it++) {
        int i = tid + it*256, r = i >> 3, d0 = (i & 7) * 8;
        *(uint4*)&smh[OFF_P + r*KSTR + d0] =
            *(const uint4*)&g_Q[base + (size_t)(qbase + r)*HD + d0];
    }
    CP_WAIT1();          // tile 0 arrived
    __syncthreads();

    uint32_t qf[4][4];
    #pragma unroll
    for (int kc = 0; kc < 4; kc++) LDSM4(qf[kc], aQ + (uint32_t)(kc*16)*2u);

    float acc[8][4];
    float s[8][4];
    #pragma unroll
    for (int nb = 0; nb < 8; nb++)
        #pragma unroll
        for (int c = 0; c < 4; c++) { acc[nb][c] = 0.f; s[nb][c] = 0.f; }
    float m0 = -1e30f, m1 = -1e30f, l0 = 0.f, l1 = 0.f;

    // S_0 = Q K_0^T
    {
        const uint32_t kb = sbase + (uint32_t)(KB(0)*2);
        #pragma unroll
        for (int kc = 0; kc < 4; kc++)
            #pragma unroll
            for (int nbp = 0; nbp < 4; nbp++) {
                uint32_t kf[4];
                LDSM4(kf, kb + aKo + (uint32_t)(nbp*16)*144u + (uint32_t)(kc*16)*2u);
                mma16(s[2*nbp  ], qf[kc], kf[0], kf[1]);
                mma16(s[2*nbp+1], qf[kc], kf[2], kf[3]);
            }
    }

    for (int j = 0; j < ntiles; j++) {
        const int n0 = j * 64;
        const uint32_t vb  = sbase + (uint32_t)(VB(j % 3)*2);
        const uint32_t kbn = sbase + (uint32_t)(KB((j+1) % 3)*2);

        CP_WAIT0();          // all staged tiles (<= j+1) arrived
        __syncthreads();     // visibility + buffer-reuse protection
        if (j + 2 < ntiles) {
            stage_kv_async(sbase, Kg, Vg, (j+2)*64, KB((j+2)%3), VB((j+2)%3), tid);
            CP_COMMIT();
        }

        if (j >= 2*qt) {   // diagonal tiles: causal mask on held S_j
            const int row = qbase + r0;
            #pragma unroll
            for (int nb = 0; nb < 8; nb++) {
                int col = n0 + nb*8 + 2*t;
                if (col     > row  ) s[nb][0] = -1e30f;
                if (col + 1 > row  ) s[nb][1] = -1e30f;
                if (col     > row+8) s[nb][2] = -1e30f;
                if (col + 1 > row+8) s[nb][3] = -1e30f;
            }
        }

        // lazy online softmax (base-2 domain)
        float mx0 = -1e30f, mx1 = -1e30f;
        #pragma unroll
        for (int nb = 0; nb < 8; nb++) {
            mx0 = fmaxf(mx0, fmaxf(s[nb][0], s[nb][1]));
            mx1 = fmaxf(mx1, fmaxf(s[nb][2], s[nb][3]));
        }
        if (__any_sync(0xffffffffu, (mx0 > m0) | (mx1 > m1))) {
            mx0 = fmaxf(mx0, __shfl_xor_sync(0xffffffffu, mx0, 1));
            mx0 = fmaxf(mx0, __shfl_xor_sync(0xffffffffu, mx0, 2));
            mx1 = fmaxf(mx1, __shfl_xor_sync(0xffffffffu, mx1, 1));
            mx1 = fmaxf(mx1, __shfl_xor_sync(0xffffffffu, mx1, 2));
            float mn0 = fmaxf(m0, mx0), mn1 = fmaxf(m1, mx1);
            float sc0 = ex2f(m0 - mn0), sc1 = ex2f(m1 - mn1);
            l0 *= sc0;  l1 *= sc1;
            #pragma unroll
            for (int nb = 0; nb < 8; nb++) {
                acc[nb][0] *= sc0; acc[nb][1] *= sc0;
                acc[nb][2] *= sc1; acc[nb][3] *= sc1;
            }
            m0 = mn0;  m1 = mn1;
        }

        // p = 2^(s-m): P A-fragments in registers; s freed
        uint32_t pa[4][4];
        #pragma unroll
        for (int kc = 0; kc < 4; kc++) {
            float p00 = ex2f(s[2*kc  ][0]-m0), p01 = ex2f(s[2*kc  ][1]-m0);
            float p02 = ex2f(s[2*kc  ][2]-m1), p03 = ex2f(s[2*kc  ][3]-m1);
            float p10 = ex2f(s[2*kc+1][0]-m0), p11 = ex2f(s[2*kc+1][1]-m0);
            float p12 = ex2f(s[2*kc+1][2]-m1), p13 = ex2f(s[2*kc+1][3]-m1);
            l0 += p00 + p01 + p10 + p11;
            l1 += p02 + p03 + p12 + p13;
            pa[kc][0] = pack2(p00, p01);
            pa[kc][1] = pack2(p02, p03);
            pa[kc][2] = pack2(p10, p11);
            pa[kc][3] = pack2(p12, p13);
        }
        #pragma unroll
        for (int nb = 0; nb < 8; nb++)
            #pragma unroll
            for (int c = 0; c < 4; c++) s[nb][c] = 0.f;

        // interleaved: S_{j+1} = Q K_{j+1}^T  ||  acc += P_j V_j
        if (j + 1 < ntiles) {
            #pragma unroll
            for (int kc = 0; kc < 4; kc++)
                #pragma unroll
                for (int nbp = 0; nbp < 4; nbp++) {
                    uint32_t kf[4], vf[4];
                    LDSM4 (kf, kbn + aKo + (uint32_t)(nbp*16)*144u + (uint32_t)(kc*16)*2u);
                    LDSM4T(vf, vb  + aVo + (uint32_t)(kc*16)*144u + (uint32_t)(nbp*16)*2u);
                    mma16(s[2*nbp    ], qf[kc], kf[0], kf[1]);
                    mma16(acc[2*nbp  ], pa[kc], vf[0], vf[1]);
                    mma16(s[2*nbp+1  ], qf[kc], kf[2], kf[3]);
                    mma16(acc[2*nbp+1], pa[kc], vf[2], vf[3]);
                }
        } else {
            #pragma unroll
            for (int kc = 0; kc < 4; kc++)
                #pragma unroll
                for (int nbp = 0; nbp < 4; nbp++) {
                    uint32_t vf[4];
                    LDSM4T(vf, vb + aVo + (uint32_t)(kc*16)*144u + (uint32_t)(nbp*16)*2u);
                    mma16(acc[2*nbp  ], pa[kc], vf[0], vf[1]);
                    mma16(acc[2*nbp+1], pa[kc], vf[2], vf[3]);
                }
        }
    }

    // epilogue: reduce l across the quad, /l, transposed coalesced store
    l0 += __shfl_xor_sync(0xffffffffu, l0, 1);
    l0 += __shfl_xor_sync(0xffffffffu, l0, 2);
    l1 += __shfl_xor_sync(0xffffffffu, l1, 1);
    l1 += __shfl_xor_sync(0xffffffffu, l1, 2);
    float inv0 = 1.f / l0, inv1 = 1.f / l1;
    #pragma unroll
    for (int nb = 0; nb < 8; nb++) {
        acc[nb][0] *= inv0; acc[nb][1] *= inv0;
        acc[nb][2] *= inv1; acc[nb][3] *= inv1;
    }
    __syncthreads();
    float* Osm = (float*)smh;
    #pragma unroll
    for (int nb = 0; nb < 8; nb++) {
        int d = nb*8 + 2*t;
        Osm[(d  )*OSTR + r0    ] = acc[nb][0];
        Osm[(d+1)*OSTR + r0    ] = acc[nb][1];
        Osm[(d  )*OSTR + r0 + 8] = acc[nb][2];
        Osm[(d+1)*OSTR + r0 + 8] = acc[nb][3];
    }
    __syncthreads();
    const size_t obase = ((size_t)b*EMB + h*HD) * NTOK + qbase;
    for (int i = tid; i < 64*128; i += 256) {
        int d = i >> 7, n = i & 127;
        out[obase + (size_t)d * NTOK + n] = Osm[d*OSTR + n];
    }
}

// ---------------------------------------------------------------------------
extern "C" void kernel_launch(void* const* d_in, const int* in_sizes, int n_in,
                              void* d_out, int out_size)
{
    const float* query = (const float*)d_in[0];
    const float* key   = (const float*)d_in[1];
    const float* Wq    = (const float*)d_in[2];
    const float* bq    = (const float*)d_in[3];
    const float* Wk    = (const float*)d_in[4];
    const float* bk    = (const float*)d_in[5];
    const float* Wv    = (const float*)d_in[6];
    const float* bv    = (const float*)d_in[7];
    float* out = (float*)d_out;

    dim3 pgrid(64, 4, 3);
    proj_mma<<<pgrid, 256>>>(query, key, Wq, bq, Wk, bk, Wv, bv);

    const int attn_smem = SMH * (int)sizeof(__half);   // 73,728 B
    cudaFuncSetAttribute(attn_mma,
                         cudaFuncAttributeMaxDynamicSharedMemorySize, attn_smem);
    dim3 agrid(32, NH, 2);
    attn_mma<<<agrid, 256, attn_smem>>>(out);
}

// round 16
// speedup vs baseline: 1.0683x; 1.0683x over previous
#include <cuda_runtime.h>
#include <cuda_fp16.h>
#include <stdint.h>

#define NH   8
#define HD   64
#define NTOK 4096
#define EMB  512
#define CIN  512

// Scratch Q/K/V in [b][h][n][d] layout, fp16.  Q pre-scaled by 0.125*log2(e).
__device__ __half g_Q[2*NH*NTOK*HD];
__device__ __half g_K[2*NH*NTOK*HD];
__device__ __half g_V[2*NH*NTOK*HD];

// ---------------------------------------------------------------------------
__device__ __forceinline__ float ex2f(float x){
    float r; asm("ex2.approx.ftz.f32 %0, %1;" : "=f"(r) : "f"(x)); return r;
}
__device__ __forceinline__ uint32_t smem_u32(const void* p) {
    uint32_t a;
    asm("{ .reg .u64 t; cvta.to.shared.u64 t, %1; cvt.u32.u64 %0, t; }" : "=r"(a) : "l"(p));
    return a;
}
__device__ __forceinline__ uint32_t pack2(float x, float y){
    __half2 h = __floats2half2_rn(x, y);
    return *(uint32_t*)&h;
}
// fp16 mma, fp32 accum (D += A*B)
__device__ __forceinline__ void mma16(float* c, const uint32_t* a, uint32_t b0, uint32_t b1){
    asm volatile("mma.sync.aligned.m16n8k16.row.col.f32.f16.f16.f32 "
        "{%0,%1,%2,%3},{%4,%5,%6,%7},{%8,%9},{%0,%1,%2,%3};"
        : "+f"(c[0]),"+f"(c[1]),"+f"(c[2]),"+f"(c[3])
        : "r"(a[0]),"r"(a[1]),"r"(a[2]),"r"(a[3]),"r"(b0),"r"(b1));
}
// fp16 mma, D = A*B (C = 0) — skips accumulator zero-init
__device__ __forceinline__ void mma16z(float* c, const uint32_t* a, uint32_t b0, uint32_t b1){
    asm volatile("mma.sync.aligned.m16n8k16.row.col.f32.f16.f16.f32 "
        "{%0,%1,%2,%3},{%4,%5,%6,%7},{%8,%9},{%10,%11,%12,%13};"
        : "=f"(c[0]),"=f"(c[1]),"=f"(c[2]),"=f"(c[3])
        : "r"(a[0]),"r"(a[1]),"r"(a[2]),"r"(a[3]),"r"(b0),"r"(b1),
          "f"(0.f),"f"(0.f),"f"(0.f),"f"(0.f));
}
#define LDSM4(r, a) \
    asm volatile("ldmatrix.sync.aligned.m8n8.x4.shared.b16 {%0,%1,%2,%3}, [%4];" \
        : "=r"((r)[0]),"=r"((r)[1]),"=r"((r)[2]),"=r"((r)[3]) : "r"(a))
#define LDSM4T(r, a) \
    asm volatile("ldmatrix.sync.aligned.m8n8.x4.trans.shared.b16 {%0,%1,%2,%3}, [%4];" \
        : "=r"((r)[0]),"=r"((r)[1]),"=r"((r)[2]),"=r"((r)[3]) : "r"(a))
#define CP16(dst, src) asm volatile("cp.async.cg.shared.global [%0], [%1], 16;" :: "r"(dst), "l"(src) : "memory")
#define CP_COMMIT()    asm volatile("cp.async.commit_group;" ::: "memory")
#define CP_WAIT0()     asm volatile("cp.async.wait_group 0;" ::: "memory")

// ---------------------------------------------------------------------------
// Projection (fp16 mma + ldmatrix): O[b][h][n][d] = X_tok @ W^T + bias.
// (unchanged: ~60 us, near memory floor)
// ---------------------------------------------------------------------------
#define XSTR 136
#define WSTR 24

__global__ __launch_bounds__(256, 2) void proj_mma(
    const float* __restrict__ query, const float* __restrict__ key,
    const float* __restrict__ Wq, const float* __restrict__ bq,
    const float* __restrict__ Wk, const float* __restrict__ bk,
    const float* __restrict__ Wv, const float* __restrict__ bv)
{
    const int z = blockIdx.z;
    const float* X    = (z == 0) ? query : key;
    const float* W    = (z == 0) ? Wq : (z == 1 ? Wk : Wv);
    const float* bias = (z == 0) ? bq : (z == 1 ? bk : bv);
    __half* O         = (z == 0) ? g_Q : (z == 1 ? g_K : g_V);
    const float osc   = (z == 0) ? 0.18033688011112042f : 1.0f;  // 0.125*log2(e)

    const int b  = blockIdx.x >> 5;
    const int n0 = (blockIdx.x & 31) * 128;
    const int e0 = blockIdx.y * 128;

    __shared__ __align__(16) __half Xs[2][16*XSTR];
    __shared__ __align__(16) __half Ws[2][128*WSTR];

    const int tid = threadIdx.x, lane = tid & 31, w = tid >> 5;
    const int g = lane >> 2, t = lane & 3;
    const int wm = w >> 1, wn = w & 1;
    const int i8 = lane >> 3, lr = lane & 7;

    const int xc = tid >> 4, xn = (tid & 15) * 8;
    const int we = tid >> 1, wc = (tid & 1) * 8;

    const uint32_t aoff = (uint32_t)(((i8 >> 1)*8 + lr)*XSTR + (i8 & 1)*8);
    const uint32_t boff = (uint32_t)(((i8 >> 1)*8 + lr)*WSTR + (i8 & 1)*8);

    const size_t xbase = (size_t)b * CIN * NTOK;

    float acc[2][8][4];
    #pragma unroll
    for (int mb = 0; mb < 2; mb++)
        #pragma unroll
        for (int nb = 0; nb < 8; nb++)
            #pragma unroll
            for (int c = 0; c < 4; c++) acc[mb][nb][c] = 0.f;

    float4 xv0 = *(const float4*)&X[xbase + (size_t)xc * NTOK + n0 + xn];
    float4 xv1 = *(const float4*)&X[xbase + (size_t)xc * NTOK + n0 + xn + 4];
    float4 wv0 = *(const float4*)&W[(size_t)(e0 + we) * CIN + wc];
    float4 wv1 = *(const float4*)&W[(size_t)(e0 + we) * CIN + wc + 4];

    for (int kt = 0; kt < CIN/16; kt++) {
        const int cur = kt & 1;
        {
            uint4 ux = { pack2(xv0.x, xv0.y), pack2(xv0.z, xv0.w),
                         pack2(xv1.x, xv1.y), pack2(xv1.z, xv1.w) };
            *(uint4*)&Xs[cur][xc*XSTR + xn] = ux;
            uint4 uw = { pack2(wv0.x, wv0.y), pack2(wv0.z, wv0.w),
                         pack2(wv1.x, wv1.y), pack2(wv1.z, wv1.w) };
            *(uint4*)&Ws[cur][we*WSTR + wc] = uw;
        }
        __syncthreads();
        if (kt + 1 < CIN/16) {
            const int c0 = (kt + 1) * 16;
            xv0 = *(const float4*)&X[xbase + (size_t)(c0 + xc) * NTOK + n0 + xn];
            xv1 = *(const float4*)&X[xbase + (size_t)(c0 + xc) * NTOK + n0 + xn + 4];
            wv0 = *(const float4*)&W[(size_t)(e0 + we) * CIN + c0 + wc];
            wv1 = *(const float4*)&W[(size_t)(e0 + we) * CIN + c0 + wc + 4];
        }
        const uint32_t sX = smem_u32(&Xs[cur][0]);
        const uint32_t sW = smem_u32(&Ws[cur][0]);
        uint32_t a[2][4];
        #pragma unroll
        for (int mb = 0; mb < 2; mb++)
            LDSM4T(a[mb], sX + 2u*(aoff + (uint32_t)(wm*32 + mb*16)));
        #pragma unroll
        for (int nbp = 0; nbp < 4; nbp++) {
            uint32_t bf[4];
            LDSM4(bf, sW + 2u*(boff + (uint32_t)((wn*64 + nbp*16)*WSTR)));
            #pragma unroll
            for (int mb = 0; mb < 2; mb++) {
                mma16(acc[mb][2*nbp  ], a[mb], bf[0], bf[1]);
                mma16(acc[mb][2*nbp+1], a[mb], bf[2], bf[3]);
            }
        }
    }

    #pragma unroll
    for (int mb = 0; mb < 2; mb++) {
        #pragma unroll
        for (int nb = 0; nb < 8; nb++) {
            int e = e0 + wn*64 + nb*8 + 2*t;
            float2 bb = *(const float2*)&bias[e];
            int h = e >> 6, d = e & 63;
            int n = n0 + wm*32 + mb*16 + g;
            __half* o0 = &O[(((size_t)b*NH + h)*NTOK + n)*HD + d];
            *(__half2*)o0 = __floats2half2_rn((acc[mb][nb][0] + bb.x) * osc,
                                              (acc[mb][nb][1] + bb.y) * osc);
            *(__half2*)(o0 + 8*HD) = __floats2half2_rn((acc[mb][nb][2] + bb.x) * osc,
                                                       (acc[mb][nb][3] + bb.y) * osc);
        }
    }
}

// ---------------------------------------------------------------------------
// Flash attention, fp16 mma + ldmatrix, cp.async double-buffered K/V.
// 4-warp CTAs (128 thr), 64-row Q tiles, 4 CTAs/SM: smaller barrier groups,
// independent CTAs hide each other's softmax/barrier phases.
// P stays in registers; lazy softmax; mma16z kills s zero-init.
// ---------------------------------------------------------------------------
#define KSTR 72
#define OFF_K0 0
#define OFF_K1 (64*KSTR)           // 4608
#define OFF_V0 (2*64*KSTR)         // 9216
#define OFF_V1 (3*64*KSTR)         // 13824
#define OFF_P  (4*64*KSTR)         // 18432  (Q stage / fp32 out stage)
#define SMH    (OFF_P + 64*KSTR)   // 23040 halves = 46080 B
#define OSTR   132

__device__ __forceinline__ void stage_kv_async(uint32_t sb, const __half* Kg, const __half* Vg,
                                               int n0, int kOff, int vOff, int tid)
{
    #pragma unroll
    for (int it = 0; it < 4; it++) {
        int i = tid + it*128, r = i >> 3, c8 = (i & 7) * 8;
        CP16(sb + (uint32_t)(kOff + r*KSTR + c8)*2u, Kg + (size_t)(n0 + r)*HD + c8);
        CP16(sb + (uint32_t)(vOff + r*KSTR + c8)*2u, Vg + (size_t)(n0 + r)*HD + c8);
    }
}

__global__ __launch_bounds__(128, 4) void attn_mma(float* __restrict__ out)
{
    const int qt = 63 - (int)blockIdx.x;   // big tiles first
    const int h  = blockIdx.y;
    const int b  = blockIdx.z;

    extern __shared__ __align__(16) __half smh[];
    const uint32_t sbase = smem_u32(smh);

    const int tid = threadIdx.x, lane = tid & 31, w = tid >> 5;   // w in 0..3
    const int g = lane >> 2, t = lane & 3;
    const int r0 = w*16 + g;
    const int m  = lane >> 3, lr = lane & 7;

    // ldmatrix per-lane addresses (row stride 144 B)
    const uint32_t aQ  = sbase + (uint32_t)(OFF_P*2) + (uint32_t)(w*16 + (m&1)*8 + lr)*144u + (uint32_t)((m>>1)*8)*2u;
    const uint32_t aKo = (uint32_t)((m>>1)*8 + lr)*144u + (uint32_t)((m&1)*8)*2u;   // + buf base
    const uint32_t aVo = (uint32_t)((m&1)*8 + lr)*144u + (uint32_t)((m>>1)*8)*2u;   // + buf base

    const size_t base  = ((size_t)(b*NH + h)) * NTOK * HD;
    const int    qbase = qt * 64;
    const __half* Kg = g_K + base;
    const __half* Vg = g_V + base;

    // stage K/V tile 0 (async) + Q (sync)
    stage_kv_async(sbase, Kg, Vg, 0, OFF_K0, OFF_V0, tid);
    CP_COMMIT();
    #pragma unroll
    for (int it = 0; it < 4; it++) {
        int i = tid + it*128, r = i >> 3, d0 = (i & 7) * 8;
        *(uint4*)&smh[OFF_P + r*KSTR + d0] =
            *(const uint4*)&g_Q[base + (size_t)(qbase + r)*HD + d0];
    }
    __syncthreads();

    uint32_t qf[4][4];
    #pragma unroll
    for (int kc = 0; kc < 4; kc++) LDSM4(qf[kc], aQ + (uint32_t)(kc*16)*2u);

    float acc[8][4];
    #pragma unroll
    for (int nb = 0; nb < 8; nb++)
        #pragma unroll
        for (int c = 0; c < 4; c++) acc[nb][c] = 0.f;
    float m0 = -1e30f, m1 = -1e30f, l0 = 0.f, l1 = 0.f;  // per-lane partial l

    const int ntiles = qt + 1;
    for (int j = 0; j < ntiles; j++) {
        const int n0 = j * 64;
        const uint32_t kb = sbase + (uint32_t)(((j & 1) ? OFF_K1 : OFF_K0) * 2);
        const uint32_t vb = sbase + (uint32_t)(((j & 1) ? OFF_V1 : OFF_V0) * 2);

        CP_WAIT0();
        __syncthreads();
        if (j + 1 < ntiles) {
            stage_kv_async(sbase, Kg, Vg, (j+1)*64,
                           ((j+1) & 1) ? OFF_K1 : OFF_K0,
                           ((j+1) & 1) ? OFF_V1 : OFF_V0, tid);
            CP_COMMIT();
        }

        // S = Q K^T  (kc=0 seeds via mma16z — no zero-init)
        float s[8][4];
        #pragma unroll
        for (int nbp = 0; nbp < 4; nbp++) {
            uint32_t kf[4];
            LDSM4(kf, kb + aKo + (uint32_t)(nbp*16)*144u);
            mma16z(s[2*nbp  ], qf[0], kf[0], kf[1]);
            mma16z(s[2*nbp+1], qf[0], kf[2], kf[3]);
        }
        #pragma unroll
        for (int kc = 1; kc < 4; kc++) {
            #pragma unroll
            for (int nbp = 0; nbp < 4; nbp++) {
                uint32_t kf[4];
                LDSM4(kf, kb + aKo + (uint32_t)(nbp*16)*144u + (uint32_t)(kc*16)*2u);
                mma16(s[2*nbp  ], qf[kc], kf[0], kf[1]);
                mma16(s[2*nbp+1], qf[kc], kf[2], kf[3]);
            }
        }

        if (j == qt) {   // diagonal tile: causal mask
            const int row = qbase + r0;
            #pragma unroll
            for (int nb = 0; nb < 8; nb++) {
                int col = n0 + nb*8 + 2*t;
                if (col     > row  ) s[nb][0] = -1e30f;
                if (col + 1 > row  ) s[nb][1] = -1e30f;
                if (col     > row+8) s[nb][2] = -1e30f;
                if (col + 1 > row+8) s[nb][3] = -1e30f;
            }
        }

        // lazy online softmax (base-2 domain)
        float mx0 = -1e30f, mx1 = -1e30f;
        #pragma unroll
        for (int nb = 0; nb < 8; nb++) {
            mx0 = fmaxf(mx0, fmaxf(s[nb][0], s[nb][1]));
            mx1 = fmaxf(mx1, fmaxf(s[nb][2], s[nb][3]));
        }
        if (__any_sync(0xffffffffu, (mx0 > m0) | (mx1 > m1))) {
            mx0 = fmaxf(mx0, __shfl_xor_sync(0xffffffffu, mx0, 1));
            mx0 = fmaxf(mx0, __shfl_xor_sync(0xffffffffu, mx0, 2));
            mx1 = fmaxf(mx1, __shfl_xor_sync(0xffffffffu, mx1, 1));
            mx1 = fmaxf(mx1, __shfl_xor_sync(0xffffffffu, mx1, 2));
            float mn0 = fmaxf(m0, mx0), mn1 = fmaxf(m1, mx1);
            float sc0 = ex2f(m0 - mn0), sc1 = ex2f(m1 - mn1);
            l0 *= sc0;  l1 *= sc1;
            #pragma unroll
            for (int nb = 0; nb < 8; nb++) {
                acc[nb][0] *= sc0; acc[nb][1] *= sc0;
                acc[nb][2] *= sc1; acc[nb][3] *= sc1;
            }
            m0 = mn0;  m1 = mn1;
        }

        // p = 2^(s-m); P A-fragments built directly in registers
        uint32_t pa[4][4];
        #pragma unroll
        for (int kc = 0; kc < 4; kc++) {
            float p00 = ex2f(s[2*kc  ][0]-m0), p01 = ex2f(s[2*kc  ][1]-m0);
            float p02 = ex2f(s[2*kc  ][2]-m1), p03 = ex2f(s[2*kc  ][3]-m1);
            float p10 = ex2f(s[2*kc+1][0]-m0), p11 = ex2f(s[2*kc+1][1]-m0);
            float p12 = ex2f(s[2*kc+1][2]-m1), p13 = ex2f(s[2*kc+1][3]-m1);
            l0 += p00 + p01 + p10 + p11;
            l1 += p02 + p03 + p12 + p13;
            pa[kc][0] = pack2(p00, p01);
            pa[kc][1] = pack2(p02, p03);
            pa[kc][2] = pack2(p10, p11);
            pa[kc][3] = pack2(p12, p13);
        }

        // O += P V  (A from registers, B = V via ldmatrix.trans)
        #pragma unroll
        for (int kc = 0; kc < 4; kc++) {
            #pragma unroll
            for (int nbp = 0; nbp < 4; nbp++) {
                uint32_t vf[4];
                LDSM4T(vf, vb + aVo + (uint32_t)(kc*16)*144u + (uint32_t)(nbp*16)*2u);
                mma16(acc[2*nbp  ], pa[kc], vf[0], vf[1]);
                mma16(acc[2*nbp+1], pa[kc], vf[2], vf[3]);
            }
        }
    }

    // epilogue: reduce l across the quad, /l, transposed coalesced store
    l0 += __shfl_xor_sync(0xffffffffu, l0, 1);
    l0 += __shfl_xor_sync(0xffffffffu, l0, 2);
    l1 += __shfl_xor_sync(0xffffffffu, l1, 1);
    l1 += __shfl_xor_sync(0xffffffffu, l1, 2);
    float inv0 = 1.f / l0, inv1 = 1.f / l1;
    #pragma unroll
    for (int nb = 0; nb < 8; nb++) {
        acc[nb][0] *= inv0; acc[nb][1] *= inv0;
        acc[nb][2] *= inv1; acc[nb][3] *= inv1;
    }
    __syncthreads();
    float* Osm = (float*)smh;
    #pragma unroll
    for (int nb = 0; nb < 8; nb++) {
        int d = nb*8 + 2*t;
        Osm[(d  )*OSTR + r0    ] = acc[nb][0];
        Osm[(d+1)*OSTR + r0    ] = acc[nb][1];
        Osm[(d  )*OSTR + r0 + 8] = acc[nb][2];
        Osm[(d+1)*OSTR + r0 + 8] = acc[nb][3];
    }
    __syncthreads();
    const size_t obase = ((size_t)b*EMB + h*HD) * NTOK + qbase;
    for (int i = tid; i < 64*64; i += 128) {
        int d = i >> 6, n = i & 63;
        out[obase + (size_t)d * NTOK + n] = Osm[d*OSTR + n];
    }
}

// ---------------------------------------------------------------------------
extern "C" void kernel_launch(void* const* d_in, const int* in_sizes, int n_in,
                              void* d_out, int out_size)
{
    const float* query = (const float*)d_in[0];
    const float* key   = (const float*)d_in[1];
    const float* Wq    = (const float*)d_in[2];
    const float* bq    = (const float*)d_in[3];
    const float* Wk    = (const float*)d_in[4];
    const float* bk    = (const float*)d_in[5];
    const float* Wv    = (const float*)d_in[6];
    const float* bv    = (const float*)d_in[7];
    float* out = (float*)d_out;

    dim3 pgrid(64, 4, 3);
    proj_mma<<<pgrid, 256>>>(query, key, Wq, bq, Wk, bk, Wv, bv);

    const int attn_smem = SMH * (int)sizeof(__half);   // 46,080 B
    cudaFuncSetAttribute(attn_mma,
                         cudaFuncAttributeMaxDynamicSharedMemorySize, attn_smem);
    dim3 agrid(64, NH, 2);
    attn_mma<<<agrid, 128, attn_smem>>>(out);
}